// round 2
// baseline (speedup 1.0000x reference)
#include <cuda_runtime.h>
#include <cuda_bf16.h>
#include <math.h>

static constexpr int NN_  = 4900;
static constexpr int NB1  = 708;
static constexpr int NB2  = 4192;   // 4900 - 708
static constexpr int DIN  = 512;
static constexpr int DOUT = 256;
static constexpr long QK  = (long)NN_ * NN_;

#define CDIV(a,b) (((a)+(b)-1)/(b))

// ---------------- scratch (single static device buffer, offsets in floats) ----------------
static constexpr long O_RP = 0;                         // 4*256
static constexpr long O_HQ = O_RP + 4L*256;             // N*256
static constexpr long O_HK = O_HQ + (long)NN_*DOUT;
static constexpr long O_V  = O_HK + (long)NN_*DOUT;
static constexpr long O_H  = O_V  + (long)NN_*DOUT;
static constexpr long O_QG = O_H  + (long)NN_*DOUT;     // [2][4][N][64]
static constexpr long O_CT = O_QG + 2L*4*NN_*64;        // [512][708]
static constexpr long O_CB = O_CT + 512L*NB1;           // [512][4192]
static constexpr long O_BT = O_CB + 512L*NB2;           // [512][N]
static constexpr long O_BB = O_BT + 512L*NN_;           // [512][N]
static constexpr long O_VG = O_BB + 512L*NN_;           // [4][N][64]
static constexpr long O_M  = O_VG + 4L*NN_*64;          // [N][256]
static constexpr long O_HM = O_M  + (long)NN_*DOUT;     // [N][512]
static constexpr long O_BE = O_HM + (long)NN_*512;      // [N][256]
static constexpr long O_OU = O_BE + (long)NN_*DOUT;     // [N][256]
static constexpr long O_T  = O_OU + (long)NN_*DOUT;     // [N][256]
static constexpr long O_AL = O_T  + (long)NN_*DOUT;     // [4][N][N]
static constexpr long TOTAL_F = O_AL + 4L*QK;

__device__ float g_buf[TOTAL_F];

// ---------------- generic tiled fp32 GEMM: C = act( A0@B0 (+ A1@B1) + bias ) -------------
// All matrices row-major. Optional z-batching via per-operand z strides.
template<int BM,int BN,int BK,int TM,int TN>
__global__ void __launch_bounds__((BM/TM)*(BN/TN))
sgemm(const float* __restrict__ A0, int lda0, long zsA0,
      const float* __restrict__ B0, int ldb0, long zsB0, int K0,
      const float* __restrict__ A1, int lda1, long zsA1,
      const float* __restrict__ B1, int ldb1, long zsB1, int K1,
      const float* __restrict__ bias,
      float* __restrict__ C, int ldc, long zsC,
      int M, int N, int act)
{
    constexpr int THREADS = (BM/TM)*(BN/TN);
    __shared__ float As[BK][BM+4];
    __shared__ float Bs[BK][BN+4];

    const int z = blockIdx.z;
    A0 += (long)z * zsA0;
    B0 += (long)z * zsB0;
    if (A1) A1 += (long)z * zsA1;
    if (B1) B1 += (long)z * zsB1;
    C  += (long)z * zsC;

    const int bm = blockIdx.y * BM;
    const int bn = blockIdx.x * BN;
    const int tid = threadIdx.x;
    const int tx = tid % (BN/TN);
    const int ty = tid / (BN/TN);

    float acc[TM][TN];
    #pragma unroll
    for (int i=0;i<TM;i++)
        #pragma unroll
        for (int j=0;j<TN;j++) acc[i][j] = 0.f;

    for (int seg = 0; seg < 2; seg++) {
        const float* A = seg ? A1 : A0;
        const float* B = seg ? B1 : B0;
        const int K   = seg ? K1 : K0;
        const int lda = seg ? lda1 : lda0;
        const int ldb = seg ? ldb1 : ldb0;
        if (K <= 0) continue;

        for (int k0 = 0; k0 < K; k0 += BK) {
            #pragma unroll
            for (int i = tid; i < BM*BK; i += THREADS) {
                int m  = i / BK, kk = i % BK;
                int gm = bm + m, gk = k0 + kk;
                As[kk][m] = (gm < M && gk < K) ? A[(long)gm*lda + gk] : 0.f;
            }
            #pragma unroll
            for (int i = tid; i < BK*BN; i += THREADS) {
                int kk = i / BN, n = i % BN;
                int gk = k0 + kk, gn = bn + n;
                Bs[kk][n] = (gk < K && gn < N) ? B[(long)gk*ldb + gn] : 0.f;
            }
            __syncthreads();

            #pragma unroll
            for (int kk = 0; kk < BK; kk++) {
                float ar[TM], br[TN];
                #pragma unroll
                for (int i=0;i<TM;i++) ar[i] = As[kk][ty*TM+i];
                #pragma unroll
                for (int j=0;j<TN;j++) br[j] = Bs[kk][tx*TN+j];
                #pragma unroll
                for (int i=0;i<TM;i++)
                    #pragma unroll
                    for (int j=0;j<TN;j++) acc[i][j] += ar[i]*br[j];
            }
            __syncthreads();
        }
    }

    #pragma unroll
    for (int i=0;i<TM;i++) {
        int gm = bm + ty*TM + i;
        if (gm >= M) continue;
        #pragma unroll
        for (int j=0;j<TN;j++) {
            int gn = bn + tx*TN + j;
            if (gn >= N) continue;
            float v = acc[i][j] + (bias ? bias[gn] : 0.f);
            if (act == 1) v = 1.f / (1.f + __expf(-v));
            C[(long)gm*ldc + gn] = v;
        }
    }
}

// ---------------- gathers -----------------------------------------------------------------
// Qg[t][h][q][d]: modulated+head-gathered Q, scale 0.5 folded in.
__global__ void k_gatherQ(const float* __restrict__ hQ, const float* __restrict__ rp,
                          const int* __restrict__ flag, float* __restrict__ Qg)
{
    int idx = blockIdx.x*256 + threadIdx.x;
    if (idx >= 2*4*NN_*64) return;
    int d = idx & 63;
    int q = (idx >> 6) % NN_;
    int h = ((idx >> 6) / NN_) & 3;
    int t = idx / (4*NN_*64);
    int ridx = (flag[0] != 0) ? 1 : 0;
    int row, col, rsel;
    if (q < NB1) { row = h*177 + (q>>2);            col = ((q&3)<<6) + d; rsel = (t==0) ? ridx : 2; }
    else { int qq = q - NB1; row = NB1 + h*1048 + (qq>>2); col = ((qq&3)<<6) + d; rsel = (t==0) ? 2 : 3; }
    Qg[idx] = hQ[row*256 + col] * rp[rsel*256 + col] * 0.5f;
}

// CtopT[s*256+h*64+d][k], k<708 : gathered/modulated K (top rows). s=0 -> rp[ridx], s=1 -> rp[2]
__global__ void k_gatherCtop(const float* __restrict__ hK, const float* __restrict__ rp,
                             const int* __restrict__ flag, float* __restrict__ CT)
{
    int idx = blockIdx.x*256 + threadIdx.x;
    if (idx >= 512*NB1) return;
    int k = idx % NB1, rowi = idx / NB1;
    int s = rowi >> 8, hd = rowi & 255, h = hd >> 6, d = hd & 63;
    int ridx = (flag[0] != 0) ? 1 : 0;
    int rsel = (s==0) ? ridx : 2;
    int col = ((k&3)<<6) + d;
    CT[idx] = hK[(h*177 + (k>>2))*256 + col] * rp[rsel*256 + col];
}

// CbotT[s*256+h*64+d][k], k<4192 : gathered K (bottom rows). s=0 -> rp[2], s=1 -> rp[3]
__global__ void k_gatherCbot(const float* __restrict__ hK, const float* __restrict__ rp,
                             float* __restrict__ CB)
{
    int idx = blockIdx.x*256 + threadIdx.x;
    if (idx >= 512*NB2) return;
    int k = idx % NB2, rowi = idx / NB2;
    int s = rowi >> 8, hd = rowi & 255, h = hd >> 6, d = hd & 63;
    int rsel = (s==0) ? 2 : 3;
    int col = ((k&3)<<6) + d;
    CB[idx] = hK[(NB1 + h*1048 + (k>>2))*256 + col] * rp[rsel*256 + col];
}

// Vg[h][k][d] = V[h*1225 + k/4, (k%4)*64 + d]
__global__ void k_gatherV(const float* __restrict__ V, float* __restrict__ Vg)
{
    int idx = blockIdx.x*256 + threadIdx.x;
    if (idx >= 4*NN_*64) return;
    int d = idx & 63;
    int k = (idx >> 6) % NN_;
    int h = (idx >> 6) / NN_;
    Vg[idx] = V[(h*1225 + (k>>2))*256 + ((k&3)<<6) + d];
}

// ---------------- softmax over head axis (axis 0) -----------------------------------------
__global__ void k_softmax(float* __restrict__ al)
{
    long i = (long)blockIdx.x*256 + threadIdx.x;
    if (i >= QK) return;
    float a0 = al[i], a1 = al[i+QK], a2 = al[i+2*QK], a3 = al[i+3*QK];
    float mx = fmaxf(fmaxf(a0,a1), fmaxf(a2,a3));
    float e0 = __expf(a0-mx), e1 = __expf(a1-mx), e2 = __expf(a2-mx), e3 = __expf(a3-mx);
    float inv = 1.f / (e0+e1+e2+e3);
    al[i] = e0*inv; al[i+QK] = e1*inv; al[i+2*QK] = e2*inv; al[i+3*QK] = e3*inv;
}

// ---------------- layernorm helpers -------------------------------------------------------
__device__ __forceinline__ float blk_sum(float v)
{
    __shared__ float sw[8];
    #pragma unroll
    for (int o=16;o;o>>=1) v += __shfl_xor_sync(0xffffffffu, v, o);
    if ((threadIdx.x & 31) == 0) sw[threadIdx.x >> 5] = v;
    __syncthreads();
    float r = 0.f;
    if (threadIdx.x < 32) {
        r = (threadIdx.x < 8) ? sw[threadIdx.x] : 0.f;
        #pragma unroll
        for (int o=4;o;o>>=1) r += __shfl_xor_sync(0xffffffffu, r, o);
        if (threadIdx.x == 0) sw[0] = r;
    }
    __syncthreads();
    r = sw[0];
    __syncthreads();
    return r;
}

// m_ln = LN(relu(m)); pack HM = [H | m_ln]
__global__ void k_relu_ln_pack(const float* __restrict__ m, const float* __restrict__ H,
                               const float* __restrict__ gg, const float* __restrict__ bb,
                               float* __restrict__ HM)
{
    int row = blockIdx.x, tid = threadIdx.x;
    float x = fmaxf(m[row*256 + tid], 0.f);
    float s1 = blk_sum(x);
    float s2 = blk_sum(x*x);
    float mean = s1 * (1.f/256.f);
    float var  = s2 * (1.f/256.f) - mean*mean;
    float y = (x - mean) * rsqrtf(var + 1e-5f) * gg[tid] + bb[tid];
    HM[row*512 + 256 + tid] = y;
    HM[row*512 + tid]       = H[row*256 + tid];
}

__global__ void k_gate(const float* __restrict__ beta, const float* __restrict__ HM,
                       const float* __restrict__ H, float* __restrict__ out)
{
    int i = blockIdx.x*256 + threadIdx.x;
    if (i >= NN_*DOUT) return;
    int r = i >> 8, c = i & 255;
    float be = beta[i];
    float mv = HM[r*512 + 256 + c];
    out[i] = be*mv + (1.f - be)*H[i];
}

__global__ void k_ln_tanh(float* __restrict__ t, const float* __restrict__ gg,
                          const float* __restrict__ bb)
{
    int row = blockIdx.x, tid = threadIdx.x;
    float x = t[row*256 + tid];
    float s1 = blk_sum(x);
    float s2 = blk_sum(x*x);
    float mean = s1 * (1.f/256.f);
    float var  = s2 * (1.f/256.f) - mean*mean;
    t[row*256 + tid] = tanhf((x - mean) * rsqrtf(var + 1e-6f) * gg[tid] + bb[tid]);
}

// ---------------- host --------------------------------------------------------------------
extern "C" void kernel_launch(void* const* d_in, const int* in_sizes, int n_in,
                              void* d_out, int out_size)
{
    const float* feature = (const float*)d_in[0];
    const float* adj     = (const float*)d_in[1];
    const float* r       = (const float*)d_in[2];
    const float* Wq = (const float*)d_in[3];  const float* bq = (const float*)d_in[4];
    const float* Wk = (const float*)d_in[5];  const float* bk = (const float*)d_in[6];
    const float* Wv = (const float*)d_in[7];  const float* bv = (const float*)d_in[8];
    const float* Ww = (const float*)d_in[9];  const float* bw = (const float*)d_in[10];
    const float* Wr = (const float*)d_in[11]; const float* br = (const float*)d_in[12];
    const float* Wbeta = (const float*)d_in[13]; const float* bbeta = (const float*)d_in[14];
    const float* ln1g = (const float*)d_in[15]; const float* ln1b = (const float*)d_in[16];
    const float* w1 = (const float*)d_in[17]; const float* b1 = (const float*)d_in[18];
    const float* ln2g = (const float*)d_in[19]; const float* ln2b = (const float*)d_in[20];
    const float* w2 = (const float*)d_in[21];
    const int*   flag = (const int*)d_in[22];
    float* out = (float*)d_out;

    float* g = nullptr;
    cudaGetSymbolAddress((void**)&g, g_buf);
    float* rp   = g + O_RP;
    float* hQ   = g + O_HQ;
    float* hK   = g + O_HK;
    float* V    = g + O_V;
    float* H    = g + O_H;
    float* Qg   = g + O_QG;
    float* CT   = g + O_CT;
    float* CB   = g + O_CB;
    float* Bt   = g + O_BT;
    float* Bb   = g + O_BB;
    float* Vg   = g + O_VG;
    float* M_   = g + O_M;
    float* HM   = g + O_HM;
    float* BE   = g + O_BE;
    float* OU   = g + O_OU;
    float* T_   = g + O_T;
    float* AL   = g + O_AL;

    // 1) rp = r @ Wr + br                         [4,256] = [4,256]@[256,256]
    sgemm<64,64,16,4,4><<<dim3(4,1,1),256>>>(r,256,0, Wr,256,0,256,
        nullptr,0,0,nullptr,0,0,0, br, rp,256,0, 4,256,0);

    // 2) projections: hQ/hK/V/H = feature @ W* + b*    [4900,256]
    sgemm<64,64,16,4,4><<<dim3(4,77,1),256>>>(feature,512,0, Wq,256,0,512,
        nullptr,0,0,nullptr,0,0,0, bq, hQ,256,0, NN_,256,0);
    sgemm<64,64,16,4,4><<<dim3(4,77,1),256>>>(feature,512,0, Wk,256,0,512,
        nullptr,0,0,nullptr,0,0,0, bk, hK,256,0, NN_,256,0);
    sgemm<64,64,16,4,4><<<dim3(4,77,1),256>>>(feature,512,0, Wv,256,0,512,
        nullptr,0,0,nullptr,0,0,0, bv, V,256,0, NN_,256,0);
    sgemm<64,64,16,4,4><<<dim3(4,77,1),256>>>(feature,512,0, Ww,256,0,512,
        nullptr,0,0,nullptr,0,0,0, bw, H,256,0, NN_,256,0);

    // 3) gathers
    k_gatherQ  <<<CDIV(2*4*NN_*64,256),256>>>(hQ, rp, flag, Qg);
    k_gatherCtop<<<CDIV(512*NB1,256),256>>>(hK, rp, flag, CT);
    k_gatherCbot<<<CDIV(512*NB2,256),256>>>(hK, rp, CB);
    k_gatherV  <<<CDIV(4*NN_*64,256),256>>>(V, Vg);

    // 4) B-build: Bt = CT @ adj[0:708,:]   Bb = CB @ adj[708:,:]      [512,4900]
    sgemm<128,128,8,8,8><<<dim3(39,4,1),256>>>(CT,NB1,0, adj,NN_,0,NB1,
        nullptr,0,0,nullptr,0,0,0, nullptr, Bt,NN_,0, 512,NN_,0);
    sgemm<128,128,8,8,8><<<dim3(39,4,1),256>>>(CB,NB2,0, adj + (long)NB1*NN_,NN_,0,NB2,
        nullptr,0,0,nullptr,0,0,0, nullptr, Bb,NN_,0, 512,NN_,0);

    // 5) alpha[h] = Qg[0][h] @ Bt[boff+h*64] + Qg[1][h] @ Bb[boff+h*64]   (z = head)
    //    q-block 1 (rows 0..707, boff=0)
    sgemm<128,128,8,8,8><<<dim3(39,6,4),256>>>(
        Qg,            64, (long)NN_*64,  Bt,             NN_, 64L*NN_, 64,
        Qg+4L*NN_*64,  64, (long)NN_*64,  Bb,             NN_, 64L*NN_, 64,
        nullptr, AL, NN_, QK, NB1, NN_, 0);
    //    q-block 2 (rows 708.., boff=256)
    sgemm<128,128,8,8,8><<<dim3(39,33,4),256>>>(
        Qg + (long)NB1*64,           64, (long)NN_*64,  Bt + 256L*NN_, NN_, 64L*NN_, 64,
        Qg + 4L*NN_*64 + (long)NB1*64,64, (long)NN_*64, Bb + 256L*NN_, NN_, 64L*NN_, 64,
        nullptr, AL + (long)NB1*NN_, NN_, QK, NB2, NN_, 0);

    // 6) softmax over heads at each (q,k)
    k_softmax<<<(int)CDIV(QK,256),256>>>(AL);

    // 7) m[h] = w[h] @ Vg[h]  -> written directly into [N,256] layout (col offset h*64 via zsC)
    sgemm<128,64,8,8,4><<<dim3(1,39,4),256>>>(
        AL, NN_, QK,  Vg, 64, (long)NN_*64, NN_,
        nullptr,0,0, nullptr,0,0,0, nullptr, M_, 256, 64, NN_, 64, 0);

    // 8) m_ln = LN(relu(m)); HM = [H | m_ln]
    k_relu_ln_pack<<<NN_,256>>>(M_, H, ln1g, ln1b, HM);

    // 9) beta = sigmoid(HM @ Wbeta + bbeta)
    sgemm<64,64,16,4,4><<<dim3(4,77,1),256>>>(HM,512,0, Wbeta,256,0,512,
        nullptr,0,0,nullptr,0,0,0, bbeta, BE,256,0, NN_,256,1);

    // 10) out = beta*m_ln + (1-beta)*H
    k_gate<<<CDIV(NN_*DOUT,256),256>>>(BE, HM, H, OU);

    // 11) t = out @ w1 + b1
    sgemm<64,64,16,4,4><<<dim3(4,77,1),256>>>(OU,256,0, w1,256,0,256,
        nullptr,0,0,nullptr,0,0,0, b1, T_,256,0, NN_,256,0);

    // 12) t = tanh(LN(t))
    k_ln_tanh<<<NN_,256>>>(T_, ln2g, ln2b);

    // 13) final = t @ w2 -> d_out
    sgemm<64,64,16,4,4><<<dim3(4,77,1),256>>>(T_,256,0, w2,256,0,256,
        nullptr,0,0,nullptr,0,0,0, nullptr, out,256,0, NN_,256,0);
}

// round 3
// speedup vs baseline: 3.7071x; 3.7071x over previous
#include <cuda_runtime.h>
#include <cuda_bf16.h>
#include <math.h>
#include <stdint.h>

static constexpr int NN_  = 4900;
static constexpr int NB1  = 708;
static constexpr int NB2  = 4192;
static constexpr long QK  = (long)NN_ * NN_;

#define CDIV(a,b) (((a)+(b)-1)/(b))

// ---------------- scratch offsets (floats) ----------------
static constexpr long O_RP = 0;                          // [4][256]
static constexpr long O_PJ = O_RP + 1024;                // 4 x [N,256]: hQ,hK,V,H
static constexpr long O_QC = O_PJ + 4L*NN_*256;          // Qcat [4][N][128]
static constexpr long O_CT = O_QC + 4L*NN_*128;          // [512][708]
static constexpr long O_CB = O_CT + 512L*NB1;            // [512][4192]
static constexpr long O_BT = O_CB + 512L*NB2;            // [512][N]
static constexpr long O_BB = O_BT + 512L*NN_;            // [512][N]
static constexpr long O_BC = O_BB + 512L*NN_;            // [2][4][128][N]
static constexpr long O_VG = O_BC + 2L*512*NN_;          // [4][N][64]
static constexpr long O_M  = O_VG + 4L*NN_*64;           // [N][256]
static constexpr long O_HM = O_M  + (long)NN_*256;       // [N][512]
static constexpr long O_BE = O_HM + (long)NN_*512;       // [N][256]
static constexpr long O_OU = O_BE + (long)NN_*256;       // [N][256]
static constexpr long O_T  = O_OU + (long)NN_*256;       // [N][256]
static constexpr long O_WC = O_T  + (long)NN_*256;       // [4][512][256]
static constexpr long O_B4 = O_WC + 4L*512*256;          // [4][256]
static constexpr long O_AL = O_B4 + 1024;                // [4][N][N]
static constexpr long TOTAL_F = O_AL + 4L*QK;

__device__ __align__(256) float g_buf[TOTAL_F];

// ---------------- bf16 split helpers ----------------
__device__ __forceinline__ uint32_t packbf(float lo, float hi){
    uint32_t u; asm("cvt.rn.bf16x2.f32 %0, %1, %2;" : "=r"(u) : "f"(hi), "f"(lo)); return u;
}
__device__ __forceinline__ void split2(float x0, float x1, uint32_t& h, uint32_t& l){
    h = packbf(x0, x1);
    float h0 = __uint_as_float(h << 16);
    float h1 = __uint_as_float(h & 0xFFFF0000u);
    l = packbf(x0 - h0, x1 - h1);
}
__device__ __forceinline__ void mma16816(float* c, const uint32_t* a, const uint32_t* b){
    asm volatile("mma.sync.aligned.m16n8k16.row.col.f32.bf16.bf16.f32 "
        "{%0,%1,%2,%3}, {%4,%5,%6,%7}, {%8,%9}, {%0,%1,%2,%3};\n"
        : "+f"(c[0]), "+f"(c[1]), "+f"(c[2]), "+f"(c[3])
        : "r"(a[0]), "r"(a[1]), "r"(a[2]), "r"(a[3]), "r"(b[0]), "r"(b[1]));
}

// ---------------- bf16-split tensor-core GEMM ----------------
// C[z] = act( A[z] @ B[z] + bias[z] ), fp32 in/out. BM=128, 512 threads, BK=16.
template<int BN>
__global__ void __launch_bounds__(512)
bfgemm(const float* __restrict__ A, int lda, long zsA,
       const float* __restrict__ B, int ldb, long zsB,
       const float* __restrict__ bias, long zsBias,
       float* __restrict__ C, int ldc, long zsC,
       int M, int N, int K, int act)
{
    constexpr int BM = 128;
    constexpr int PA = 12;
    constexpr int PB = BN + 8;
    constexpr int NF = BN / 32;
    constexpr int MF = 2;
    constexpr int BTASK = 8 * (BN / 4);

    __shared__ uint32_t sAh[2][BM*PA], sAl[2][BM*PA];
    __shared__ uint32_t sBh[2][8*PB],  sBl[2][8*PB];

    const int z = blockIdx.z;
    A += (long)z * zsA;  B += (long)z * zsB;  C += (long)z * zsC;
    const float* bz = bias ? (bias + (long)z * zsBias) : nullptr;

    const int bm = blockIdx.y * BM;
    const int bn = blockIdx.x * BN;
    const int tid  = threadIdx.x;
    const int lane = tid & 31, wid = tid >> 5;
    const int g = lane >> 2, r = lane & 3;
    const int wm = (wid & 3) * 32;
    const int wn = (wid >> 2) * (BN / 4);
    const int am = tid >> 2, akq = tid & 3;
    const int nk = (K + 15) >> 4;

    float4 ra, rb0, rb1;

    auto ldgA = [&](int t){
        int gk = (t << 4) + akq * 4;
        if (bm + am < M && gk < K)
            ra = *reinterpret_cast<const float4*>(A + (long)(bm + am) * lda + gk);
        else ra = make_float4(0.f, 0.f, 0.f, 0.f);
    };
    auto ldgB = [&](int t){
        if (tid < BTASK){
            int bk2 = tid / (BN/4), bn4 = tid % (BN/4);
            int gk = (t << 4) + bk2 * 2;
            int gn = bn + bn4 * 4;
            if (gk < K && gn < N){
                rb0 = *reinterpret_cast<const float4*>(B + (long)gk * ldb + gn);
                rb1 = *reinterpret_cast<const float4*>(B + (long)(gk + 1) * ldb + gn);
            } else {
                rb0 = make_float4(0.f,0.f,0.f,0.f);
                rb1 = make_float4(0.f,0.f,0.f,0.f);
            }
        }
    };
    auto sts = [&](int buf){
        uint32_t h0, l0, h1, l1;
        split2(ra.x, ra.y, h0, l0);
        split2(ra.z, ra.w, h1, l1);
        *reinterpret_cast<uint2*>(&sAh[buf][am*PA + 2*akq]) = make_uint2(h0, h1);
        *reinterpret_cast<uint2*>(&sAl[buf][am*PA + 2*akq]) = make_uint2(l0, l1);
        if (tid < BTASK){
            int bk2 = tid / (BN/4), bn4 = tid % (BN/4);
            uint32_t bh[4], bl[4];
            float b0v[4] = {rb0.x, rb0.y, rb0.z, rb0.w};
            float b1v[4] = {rb1.x, rb1.y, rb1.z, rb1.w};
            #pragma unroll
            for (int j = 0; j < 4; j++) split2(b0v[j], b1v[j], bh[j], bl[j]);
            *reinterpret_cast<uint4*>(&sBh[buf][bk2*PB + bn4*4]) = make_uint4(bh[0],bh[1],bh[2],bh[3]);
            *reinterpret_cast<uint4*>(&sBl[buf][bk2*PB + bn4*4]) = make_uint4(bl[0],bl[1],bl[2],bl[3]);
        }
    };

    float acc[MF][NF][4];
    #pragma unroll
    for (int i=0;i<MF;i++)
        #pragma unroll
        for (int j=0;j<NF;j++)
            #pragma unroll
            for (int q=0;q<4;q++) acc[i][j][q] = 0.f;

    ldgA(0); ldgB(0);

    for (int t = 0; t < nk; t++){
        const int buf = t & 1;
        sts(buf);
        __syncthreads();
        if (t + 1 < nk){ ldgA(t + 1); ldgB(t + 1); }

        uint32_t ah[MF][4], al[MF][4];
        #pragma unroll
        for (int mi = 0; mi < MF; mi++){
            int m0 = wm + mi * 16;
            ah[mi][0] = sAh[buf][(m0 + g)    *PA + r];
            ah[mi][1] = sAh[buf][(m0 + 8 + g)*PA + r];
            ah[mi][2] = sAh[buf][(m0 + g)    *PA + r + 4];
            ah[mi][3] = sAh[buf][(m0 + 8 + g)*PA + r + 4];
            al[mi][0] = sAl[buf][(m0 + g)    *PA + r];
            al[mi][1] = sAl[buf][(m0 + 8 + g)*PA + r];
            al[mi][2] = sAl[buf][(m0 + g)    *PA + r + 4];
            al[mi][3] = sAl[buf][(m0 + 8 + g)*PA + r + 4];
        }
        #pragma unroll
        for (int nj = 0; nj < NF; nj++){
            int n0 = wn + nj * 8 + g;
            uint32_t bh[2], bl[2];
            bh[0] = sBh[buf][ r     *PB + n0];
            bh[1] = sBh[buf][(r + 4)*PB + n0];
            bl[0] = sBl[buf][ r     *PB + n0];
            bl[1] = sBl[buf][(r + 4)*PB + n0];
            #pragma unroll
            for (int mi = 0; mi < MF; mi++){
                mma16816(acc[mi][nj], ah[mi], bl);
                mma16816(acc[mi][nj], al[mi], bh);
                mma16816(acc[mi][nj], ah[mi], bh);
            }
        }
    }

    #pragma unroll
    for (int mi = 0; mi < MF; mi++){
        #pragma unroll
        for (int nj = 0; nj < NF; nj++){
            int gm0 = bm + wm + mi * 16 + g;
            int gn0 = bn + wn + nj * 8 + r * 2;
            const float* c = acc[mi][nj];
            #pragma unroll
            for (int q = 0; q < 4; q++){
                int gm = gm0 + (q >= 2 ? 8 : 0);
                int gn = gn0 + (q & 1);
                if (gm < M && gn < N){
                    float v = c[q] + (bz ? bz[gn] : 0.f);
                    if (act == 1) v = 1.f / (1.f + __expf(-v));
                    C[(long)gm * ldc + gn] = v;
                }
            }
        }
    }
}

// ---------------- small kernels ----------------
__global__ void k_rp(const float* __restrict__ r, const float* __restrict__ Wr,
                     const float* __restrict__ br, float* __restrict__ rp)
{
    int idx = blockIdx.x*256 + threadIdx.x;
    if (idx >= 1024) return;
    int i = idx >> 8, j = idx & 255;
    float s = br[j];
    for (int k = 0; k < 256; k++) s += r[i*256 + k] * Wr[k*256 + j];
    rp[idx] = s;
}

__global__ void k_packW(const float* __restrict__ Wq, const float* __restrict__ Wk,
                        const float* __restrict__ Wv, const float* __restrict__ Ww,
                        const float* __restrict__ bq, const float* __restrict__ bk,
                        const float* __restrict__ bv, const float* __restrict__ bw,
                        float* __restrict__ WC, float* __restrict__ B4)
{
    int idx = blockIdx.x*256 + threadIdx.x;
    if (idx < 4*512*256){
        int z = idx / (512*256), o = idx % (512*256);
        const float* s = (z==0) ? Wq : (z==1) ? Wk : (z==2) ? Wv : Ww;
        WC[idx] = s[o];
    }
    if (idx < 1024){
        int z = idx >> 8, o = idx & 255;
        const float* s = (z==0) ? bq : (z==1) ? bk : (z==2) ? bv : bw;
        B4[idx] = s[o];
    }
}

// Qcat[h][q][j]: j<64 -> t=0 modulation, j>=64 -> t=1. 0.5 scale folded in.
__global__ void k_gatherQ(const float* __restrict__ hQ, const float* __restrict__ rp,
                          const int* __restrict__ flag, float* __restrict__ Qc)
{
    long idx = (long)blockIdx.x*256 + threadIdx.x;
    if (idx >= 4L*NN_*128) return;
    int j = idx & 127, t = j >> 6, d = j & 63;
    int q = (int)((idx >> 7) % NN_);
    int h = (int)((idx >> 7) / NN_);
    int ridx = (flag[0] != 0) ? 1 : 0;
    int row, col, rsel;
    if (q < NB1) { row = h*177 + (q>>2);               col = ((q&3)<<6) + d; rsel = (t==0) ? ridx : 2; }
    else { int qq = q - NB1; row = NB1 + h*1048 + (qq>>2); col = ((qq&3)<<6) + d; rsel = (t==0) ? 2 : 3; }
    Qc[idx] = hQ[row*256 + col] * rp[rsel*256 + col] * 0.5f;
}

__global__ void k_gatherCtop(const float* __restrict__ hK, const float* __restrict__ rp,
                             const int* __restrict__ flag, float* __restrict__ CT)
{
    int idx = blockIdx.x*256 + threadIdx.x;
    if (idx >= 512*NB1) return;
    int k = idx % NB1, rowi = idx / NB1;
    int s = rowi >> 8, hd = rowi & 255, h = hd >> 6, d = hd & 63;
    int ridx = (flag[0] != 0) ? 1 : 0;
    int rsel = (s == 0) ? ridx : 2;
    int col = ((k&3)<<6) + d;
    CT[idx] = hK[(h*177 + (k>>2))*256 + col] * rp[rsel*256 + col];
}

__global__ void k_gatherCbot(const float* __restrict__ hK, const float* __restrict__ rp,
                             float* __restrict__ CB)
{
    long idx = (long)blockIdx.x*256 + threadIdx.x;
    if (idx >= 512L*NB2) return;
    int k = (int)(idx % NB2); int rowi = (int)(idx / NB2);
    int s = rowi >> 8, hd = rowi & 255, h = hd >> 6, d = hd & 63;
    int rsel = (s == 0) ? 2 : 3;
    int col = ((k&3)<<6) + d;
    CB[idx] = hK[(NB1 + h*1048 + (k>>2))*256 + col] * rp[rsel*256 + col];
}

__global__ void k_gatherV(const float* __restrict__ V, float* __restrict__ Vg)
{
    long idx = (long)blockIdx.x*256 + threadIdx.x;
    if (idx >= 4L*NN_*64) return;
    int d = idx & 63;
    int k = (int)((idx >> 6) % NN_);
    int h = (int)((idx >> 6) / NN_);
    Vg[idx] = V[(h*1225 + (k>>2))*256 + ((k&3)<<6) + d];
}

// BC[s][h][j][n]: j<64 from Bt row s*256+h*64+j, j>=64 from Bb row s*256+h*64+(j-64)
__global__ void k_scatterB(const float* __restrict__ Bt, const float* __restrict__ Bb,
                           float* __restrict__ BC)
{
    long idx = (long)blockIdx.x*256 + threadIdx.x;
    if (idx >= 2L*512*NN_) return;
    int n = (int)(idx % NN_);
    int rowo = (int)(idx / NN_);
    int j = rowo & 127;
    int h = (rowo >> 7) & 3;
    int s = rowo >> 9;
    const float* src = (j < 64) ? Bt : Bb;
    BC[idx] = src[(long)(s*256 + h*64 + (j & 63)) * NN_ + n];
}

__global__ void k_softmax(float* __restrict__ al)
{
    long i = (long)blockIdx.x*256 + threadIdx.x;
    if (i >= QK) return;
    float a0 = al[i], a1 = al[i+QK], a2 = al[i+2*QK], a3 = al[i+3*QK];
    float mx = fmaxf(fmaxf(a0,a1), fmaxf(a2,a3));
    float e0 = __expf(a0-mx), e1 = __expf(a1-mx), e2 = __expf(a2-mx), e3 = __expf(a3-mx);
    float inv = 1.f / (e0+e1+e2+e3);
    al[i] = e0*inv; al[i+QK] = e1*inv; al[i+2*QK] = e2*inv; al[i+3*QK] = e3*inv;
}

__device__ __forceinline__ float blk_sum(float v)
{
    __shared__ float sw[8];
    #pragma unroll
    for (int o=16;o;o>>=1) v += __shfl_xor_sync(0xffffffffu, v, o);
    if ((threadIdx.x & 31) == 0) sw[threadIdx.x >> 5] = v;
    __syncthreads();
    float r = 0.f;
    if (threadIdx.x < 32) {
        r = (threadIdx.x < 8) ? sw[threadIdx.x] : 0.f;
        #pragma unroll
        for (int o=4;o;o>>=1) r += __shfl_xor_sync(0xffffffffu, r, o);
        if (threadIdx.x == 0) sw[0] = r;
    }
    __syncthreads();
    r = sw[0];
    __syncthreads();
    return r;
}

__global__ void k_relu_ln_pack(const float* __restrict__ m, const float* __restrict__ H,
                               const float* __restrict__ gg, const float* __restrict__ bb,
                               float* __restrict__ HM)
{
    int row = blockIdx.x, tid = threadIdx.x;
    float x = fmaxf(m[row*256 + tid], 0.f);
    float s1 = blk_sum(x);
    float s2 = blk_sum(x*x);
    float mean = s1 * (1.f/256.f);
    float var  = s2 * (1.f/256.f) - mean*mean;
    float y = (x - mean) * rsqrtf(var + 1e-5f) * gg[tid] + bb[tid];
    HM[row*512 + 256 + tid] = y;
    HM[row*512 + tid]       = H[row*256 + tid];
}

__global__ void k_gate(const float* __restrict__ beta, const float* __restrict__ HM,
                       const float* __restrict__ H, float* __restrict__ out)
{
    int i = blockIdx.x*256 + threadIdx.x;
    if (i >= NN_*256) return;
    int r = i >> 8, c = i & 255;
    float be = beta[i];
    float mv = HM[r*512 + 256 + c];
    out[i] = be*mv + (1.f - be)*H[i];
}

__global__ void k_ln_tanh(float* __restrict__ t, const float* __restrict__ gg,
                          const float* __restrict__ bb)
{
    int row = blockIdx.x, tid = threadIdx.x;
    float x = t[row*256 + tid];
    float s1 = blk_sum(x);
    float s2 = blk_sum(x*x);
    float mean = s1 * (1.f/256.f);
    float var  = s2 * (1.f/256.f) - mean*mean;
    t[row*256 + tid] = tanhf((x - mean) * rsqrtf(var + 1e-6f) * gg[tid] + bb[tid]);
}

// ---------------- host ----------------
extern "C" void kernel_launch(void* const* d_in, const int* in_sizes, int n_in,
                              void* d_out, int out_size)
{
    const float* feature = (const float*)d_in[0];
    const float* adj     = (const float*)d_in[1];
    const float* r       = (const float*)d_in[2];
    const float* Wq = (const float*)d_in[3];  const float* bq = (const float*)d_in[4];
    const float* Wk = (const float*)d_in[5];  const float* bk = (const float*)d_in[6];
    const float* Wv = (const float*)d_in[7];  const float* bv = (const float*)d_in[8];
    const float* Ww = (const float*)d_in[9];  const float* bw = (const float*)d_in[10];
    const float* Wr = (const float*)d_in[11]; const float* br = (const float*)d_in[12];
    const float* Wbeta = (const float*)d_in[13]; const float* bbeta = (const float*)d_in[14];
    const float* ln1g = (const float*)d_in[15]; const float* ln1b = (const float*)d_in[16];
    const float* w1 = (const float*)d_in[17]; const float* b1 = (const float*)d_in[18];
    const float* ln2g = (const float*)d_in[19]; const float* ln2b = (const float*)d_in[20];
    const float* w2 = (const float*)d_in[21];
    const int*   flag = (const int*)d_in[22];
    float* out = (float*)d_out;

    float* g = nullptr;
    cudaGetSymbolAddress((void**)&g, g_buf);
    float* rp = g + O_RP;
    float* PJ = g + O_PJ;
    float* hQ = PJ;  float* hK = PJ + (long)NN_*256;
    float* V  = PJ + 2L*NN_*256;  float* H = PJ + 3L*NN_*256;
    float* Qc = g + O_QC;
    float* CT = g + O_CT;  float* CB = g + O_CB;
    float* Bt = g + O_BT;  float* Bb = g + O_BB;
    float* BC = g + O_BC;  float* Vg = g + O_VG;
    float* M_ = g + O_M;   float* HM = g + O_HM;
    float* BE = g + O_BE;  float* OU = g + O_OU;
    float* T_ = g + O_T;   float* WC = g + O_WC;
    float* B4 = g + O_B4;  float* AL = g + O_AL;

    // 0) pack weights + rp
    k_packW<<<CDIV(4*512*256,256),256>>>(Wq,Wk,Wv,Ww, bq,bk,bv,bw, WC,B4);
    k_rp<<<4,256>>>(r, Wr, br, rp);

    // 1) projections (batched z=4): PJ[z] = feature @ WC[z] + B4[z]
    bfgemm<64><<<dim3(4,39,4),512>>>(feature,512,0, WC,256,512L*256, B4,256,
        PJ,256,(long)NN_*256, NN_,256,512, 0);

    // 2) gathers
    k_gatherQ  <<<(int)CDIV(4L*NN_*128,256),256>>>(hQ, rp, flag, Qc);
    k_gatherCtop<<<CDIV(512*NB1,256),256>>>(hK, rp, flag, CT);
    k_gatherCbot<<<(int)CDIV(512L*NB2,256),256>>>(hK, rp, CB);
    k_gatherV  <<<(int)CDIV(4L*NN_*64,256),256>>>(V, Vg);

    // 3) B-build: Bt = CT @ adj[:708], Bb = CB @ adj[708:]
    bfgemm<128><<<dim3(39,4,1),512>>>(CT,NB1,0, adj,NN_,0, nullptr,0,
        Bt,NN_,0, 512,NN_,NB1, 0);
    bfgemm<128><<<dim3(39,4,1),512>>>(CB,NB2,0, adj + (long)NB1*NN_,NN_,0, nullptr,0,
        Bb,NN_,0, 512,NN_,NB2, 0);

    // 4) BC concat
    k_scatterB<<<(int)CDIV(2L*512*NN_,256),256>>>(Bt, Bb, BC);

    // 5) alpha[h] = Qc[h] @ BC[s][h]   (s=0 for q<708, s=1 for q>=708)
    bfgemm<128><<<dim3(39,6,4),512>>>(Qc,128,(long)NN_*128, BC,NN_,128L*NN_, nullptr,0,
        AL,NN_,QK, NB1,NN_,128, 0);
    bfgemm<128><<<dim3(39,33,4),512>>>(Qc + (long)NB1*128,128,(long)NN_*128,
        BC + 4L*128*NN_,NN_,128L*NN_, nullptr,0,
        AL + (long)NB1*NN_,NN_,QK, NB2,NN_,128, 0);

    // 6) softmax over heads
    k_softmax<<<(int)CDIV(QK,256),256>>>(AL);

    // 7) m[h] = alpha[h] @ Vg[h] -> M_ cols h*64..h*64+63
    bfgemm<64><<<dim3(1,39,4),512>>>(AL,NN_,QK, Vg,64,(long)NN_*64, nullptr,0,
        M_,256,64, NN_,64,NN_, 0);

    // 8) m_ln = LN(relu(m)); HM = [H | m_ln]
    k_relu_ln_pack<<<NN_,256>>>(M_, H, ln1g, ln1b, HM);

    // 9) beta = sigmoid(HM @ Wbeta + bbeta)
    bfgemm<64><<<dim3(4,39,1),512>>>(HM,512,0, Wbeta,256,0, bbeta,0,
        BE,256,0, NN_,256,512, 1);

    // 10) gate
    k_gate<<<CDIV(NN_*256,256),256>>>(BE, HM, H, OU);

    // 11) t = OU @ w1 + b1
    bfgemm<64><<<dim3(4,39,1),512>>>(OU,256,0, w1,256,0, b1,0,
        T_,256,0, NN_,256,256, 0);

    // 12) t = tanh(LN(t))
    k_ln_tanh<<<NN_,256>>>(T_, ln2g, ln2b);

    // 13) out = t @ w2
    bfgemm<64><<<dim3(4,39,1),512>>>(T_,256,0, w2,256,0, nullptr,0,
        out,256,0, NN_,256,256, 0);
}

// round 4
// speedup vs baseline: 3.7124x; 1.0014x over previous
#include <cuda_runtime.h>
#include <cuda_bf16.h>
#include <math.h>
#include <stdint.h>

static constexpr int NN_  = 4900;
static constexpr int NB1  = 708;
static constexpr int NB2  = 4192;
static constexpr long QK  = (long)NN_ * NN_;

#define CDIV(a,b) (((a)+(b)-1)/(b))

// ---------------- scratch offsets (floats) ----------------
static constexpr long O_RP = 0;                          // [4][256]
static constexpr long O_PJ = O_RP + 1024;                // 4 x [N,256]: hQ,hK,V,H
static constexpr long O_QC = O_PJ + 4L*NN_*256;          // Qcat [4][N][128]
static constexpr long O_CT = O_QC + 4L*NN_*128;          // [512][708]
static constexpr long O_CB = O_CT + 512L*NB1;            // [512][4192]
static constexpr long O_BT = O_CB + 512L*NB2;            // [512][N]
static constexpr long O_BB = O_BT + 512L*NN_;            // [512][N]
static constexpr long O_BC = O_BB + 512L*NN_;            // [2][4][128][N]
static constexpr long O_VG = O_BC + 2L*512*NN_;          // [4][N][64]
static constexpr long O_M  = O_VG + 4L*NN_*64;           // [N][256]
static constexpr long O_HM = O_M  + (long)NN_*256;       // [N][512]
static constexpr long O_BE = O_HM + (long)NN_*512;       // [N][256]
static constexpr long O_OU = O_BE + (long)NN_*256;       // [N][256]
static constexpr long O_T  = O_OU + (long)NN_*256;       // [N][256]
static constexpr long O_WC = O_T  + (long)NN_*256;       // [4][512][256]
static constexpr long O_B4 = O_WC + 4L*512*256;          // [4][256]
static constexpr long O_AL = O_B4 + 1024;                // [4][N][N]
static constexpr long TOTAL_F = O_AL + 4L*QK;

__device__ __align__(256) float g_buf[TOTAL_F];

// ---------------- bf16 split helpers ----------------
__device__ __forceinline__ uint32_t packbf(float lo, float hi){
    uint32_t u; asm("cvt.rn.bf16x2.f32 %0, %1, %2;" : "=r"(u) : "f"(hi), "f"(lo)); return u;
}
__device__ __forceinline__ void split2(float x0, float x1, uint32_t& h, uint32_t& l){
    h = packbf(x0, x1);
    float h0 = __uint_as_float(h << 16);
    float h1 = __uint_as_float(h & 0xFFFF0000u);
    l = packbf(x0 - h0, x1 - h1);
}
__device__ __forceinline__ void mma16816(float* c, const uint32_t* a, const uint32_t* b){
    asm volatile("mma.sync.aligned.m16n8k16.row.col.f32.bf16.bf16.f32 "
        "{%0,%1,%2,%3}, {%4,%5,%6,%7}, {%8,%9}, {%0,%1,%2,%3};\n"
        : "+f"(c[0]), "+f"(c[1]), "+f"(c[2]), "+f"(c[3])
        : "r"(a[0]), "r"(a[1]), "r"(a[2]), "r"(a[3]), "r"(b[0]), "r"(b[1]));
}

// ---------------- bf16-split tensor-core GEMM ----------------
// C[z] = act( A[z] @ B[z] + bias[z] ), fp32 in/out. BM=128, 512 threads, BK=16.
template<int BN>
__global__ void __launch_bounds__(512)
bfgemm(const float* __restrict__ A, int lda, long zsA,
       const float* __restrict__ B, int ldb, long zsB,
       const float* __restrict__ bias, long zsBias,
       float* __restrict__ C, int ldc, long zsC,
       int M, int N, int K, int act)
{
    constexpr int BM = 128;
    constexpr int PA = 12;
    constexpr int PB = BN + 8;
    constexpr int NF = BN / 32;
    constexpr int MF = 2;
    constexpr int BTASK = 8 * (BN / 4);

    __shared__ uint32_t sAh[2][BM*PA], sAl[2][BM*PA];
    __shared__ uint32_t sBh[2][8*PB],  sBl[2][8*PB];

    const int z = blockIdx.z;
    A += (long)z * zsA;  B += (long)z * zsB;  C += (long)z * zsC;
    const float* bz = bias ? (bias + (long)z * zsBias) : nullptr;

    const int bm = blockIdx.y * BM;
    const int bn = blockIdx.x * BN;
    const int tid  = threadIdx.x;
    const int lane = tid & 31, wid = tid >> 5;
    const int g = lane >> 2, r = lane & 3;
    const int wm = (wid & 3) * 32;
    const int wn = (wid >> 2) * (BN / 4);
    const int am = tid >> 2, akq = tid & 3;
    const int nk = (K + 15) >> 4;

    float4 ra, rb0, rb1;

    auto ldgA = [&](int t){
        int gk = (t << 4) + akq * 4;
        if (bm + am < M && gk < K)
            ra = *reinterpret_cast<const float4*>(A + (long)(bm + am) * lda + gk);
        else ra = make_float4(0.f, 0.f, 0.f, 0.f);
    };
    auto ldgB = [&](int t){
        if (tid < BTASK){
            int bk2 = tid / (BN/4), bn4 = tid % (BN/4);
            int gk = (t << 4) + bk2 * 2;
            int gn = bn + bn4 * 4;
            if (gk < K && gn < N){
                rb0 = *reinterpret_cast<const float4*>(B + (long)gk * ldb + gn);
                rb1 = *reinterpret_cast<const float4*>(B + (long)(gk + 1) * ldb + gn);
            } else {
                rb0 = make_float4(0.f,0.f,0.f,0.f);
                rb1 = make_float4(0.f,0.f,0.f,0.f);
            }
        }
    };
    auto sts = [&](int buf){
        uint32_t h0, l0, h1, l1;
        split2(ra.x, ra.y, h0, l0);
        split2(ra.z, ra.w, h1, l1);
        *reinterpret_cast<uint2*>(&sAh[buf][am*PA + 2*akq]) = make_uint2(h0, h1);
        *reinterpret_cast<uint2*>(&sAl[buf][am*PA + 2*akq]) = make_uint2(l0, l1);
        if (tid < BTASK){
            int bk2 = tid / (BN/4), bn4 = tid % (BN/4);
            uint32_t bh[4], bl[4];
            float b0v[4] = {rb0.x, rb0.y, rb0.z, rb0.w};
            float b1v[4] = {rb1.x, rb1.y, rb1.z, rb1.w};
            #pragma unroll
            for (int j = 0; j < 4; j++) split2(b0v[j], b1v[j], bh[j], bl[j]);
            *reinterpret_cast<uint4*>(&sBh[buf][bk2*PB + bn4*4]) = make_uint4(bh[0],bh[1],bh[2],bh[3]);
            *reinterpret_cast<uint4*>(&sBl[buf][bk2*PB + bn4*4]) = make_uint4(bl[0],bl[1],bl[2],bl[3]);
        }
    };

    float acc[MF][NF][4];
    #pragma unroll
    for (int i=0;i<MF;i++)
        #pragma unroll
        for (int j=0;j<NF;j++)
            #pragma unroll
            for (int q=0;q<4;q++) acc[i][j][q] = 0.f;

    ldgA(0); ldgB(0);

    for (int t = 0; t < nk; t++){
        const int buf = t & 1;
        sts(buf);
        __syncthreads();
        if (t + 1 < nk){ ldgA(t + 1); ldgB(t + 1); }

        uint32_t ah[MF][4], al[MF][4];
        #pragma unroll
        for (int mi = 0; mi < MF; mi++){
            int m0 = wm + mi * 16;
            ah[mi][0] = sAh[buf][(m0 + g)    *PA + r];
            ah[mi][1] = sAh[buf][(m0 + 8 + g)*PA + r];
            ah[mi][2] = sAh[buf][(m0 + g)    *PA + r + 4];
            ah[mi][3] = sAh[buf][(m0 + 8 + g)*PA + r + 4];
            al[mi][0] = sAl[buf][(m0 + g)    *PA + r];
            al[mi][1] = sAl[buf][(m0 + 8 + g)*PA + r];
            al[mi][2] = sAl[buf][(m0 + g)    *PA + r + 4];
            al[mi][3] = sAl[buf][(m0 + 8 + g)*PA + r + 4];
        }
        #pragma unroll
        for (int nj = 0; nj < NF; nj++){
            int n0 = wn + nj * 8 + g;
            uint32_t bh[2], bl[2];
            bh[0] = sBh[buf][ r     *PB + n0];
            bh[1] = sBh[buf][(r + 4)*PB + n0];
            bl[0] = sBl[buf][ r     *PB + n0];
            bl[1] = sBl[buf][(r + 4)*PB + n0];
            #pragma unroll
            for (int mi = 0; mi < MF; mi++){
                mma16816(acc[mi][nj], ah[mi], bl);
                mma16816(acc[mi][nj], al[mi], bh);
                mma16816(acc[mi][nj], ah[mi], bh);
            }
        }
    }

    #pragma unroll
    for (int mi = 0; mi < MF; mi++){
        #pragma unroll
        for (int nj = 0; nj < NF; nj++){
            int gm0 = bm + wm + mi * 16 + g;
            int gn0 = bn + wn + nj * 8 + r * 2;
            const float* c = acc[mi][nj];
            #pragma unroll
            for (int q = 0; q < 4; q++){
                int gm = gm0 + (q >= 2 ? 8 : 0);
                int gn = gn0 + (q & 1);
                if (gm < M && gn < N){
                    float v = c[q] + (bz ? bz[gn] : 0.f);
                    if (act == 1) v = 1.f / (1.f + __expf(-v));
                    C[(long)gm * ldc + gn] = v;
                }
            }
        }
    }
}

// ---------------- small kernels ----------------
__global__ void k_rp(const float* __restrict__ r, const float* __restrict__ Wr,
                     const float* __restrict__ br, float* __restrict__ rp)
{
    int idx = blockIdx.x*256 + threadIdx.x;
    if (idx >= 1024) return;
    int i = idx >> 8, j = idx & 255;
    float s = br[j];
    for (int k = 0; k < 256; k++) s += r[i*256 + k] * Wr[k*256 + j];
    rp[idx] = s;
}

__global__ void k_packW(const float* __restrict__ Wq, const float* __restrict__ Wk,
                        const float* __restrict__ Wv, const float* __restrict__ Ww,
                        const float* __restrict__ bq, const float* __restrict__ bk,
                        const float* __restrict__ bv, const float* __restrict__ bw,
                        float* __restrict__ WC, float* __restrict__ B4)
{
    int idx = blockIdx.x*256 + threadIdx.x;
    if (idx < 4*512*256){
        int z = idx / (512*256), o = idx % (512*256);
        const float* s = (z==0) ? Wq : (z==1) ? Wk : (z==2) ? Wv : Ww;
        WC[idx] = s[o];
    }
    if (idx < 1024){
        int z = idx >> 8, o = idx & 255;
        const float* s = (z==0) ? bq : (z==1) ? bk : (z==2) ? bv : bw;
        B4[idx] = s[o];
    }
}

// Qcat[h][q][j]: j<64 -> t=0 modulation, j>=64 -> t=1. 0.5 scale folded in.
__global__ void k_gatherQ(const float* __restrict__ hQ, const float* __restrict__ rp,
                          const int* __restrict__ flag, float* __restrict__ Qc)
{
    long idx = (long)blockIdx.x*256 + threadIdx.x;
    if (idx >= 4L*NN_*128) return;
    int j = idx & 127, t = j >> 6, d = j & 63;
    int q = (int)((idx >> 7) % NN_);
    int h = (int)((idx >> 7) / NN_);
    int ridx = (flag[0] != 0) ? 1 : 0;
    int row, col, rsel;
    if (q < NB1) { row = h*177 + (q>>2);               col = ((q&3)<<6) + d; rsel = (t==0) ? ridx : 2; }
    else { int qq = q - NB1; row = NB1 + h*1048 + (qq>>2); col = ((qq&3)<<6) + d; rsel = (t==0) ? 2 : 3; }
    Qc[idx] = hQ[row*256 + col] * rp[rsel*256 + col] * 0.5f;
}

__global__ void k_gatherCtop(const float* __restrict__ hK, const float* __restrict__ rp,
                             const int* __restrict__ flag, float* __restrict__ CT)
{
    int idx = blockIdx.x*256 + threadIdx.x;
    if (idx >= 512*NB1) return;
    int k = idx % NB1, rowi = idx / NB1;
    int s = rowi >> 8, hd = rowi & 255, h = hd >> 6, d = hd & 63;
    int ridx = (flag[0] != 0) ? 1 : 0;
    int rsel = (s == 0) ? ridx : 2;
    int col = ((k&3)<<6) + d;
    CT[idx] = hK[(h*177 + (k>>2))*256 + col] * rp[rsel*256 + col];
}

__global__ void k_gatherCbot(const float* __restrict__ hK, const float* __restrict__ rp,
                             float* __restrict__ CB)
{
    long idx = (long)blockIdx.x*256 + threadIdx.x;
    if (idx >= 512L*NB2) return;
    int k = (int)(idx % NB2); int rowi = (int)(idx / NB2);
    int s = rowi >> 8, hd = rowi & 255, h = hd >> 6, d = hd & 63;
    int rsel = (s == 0) ? 2 : 3;
    int col = ((k&3)<<6) + d;
    CB[idx] = hK[(NB1 + h*1048 + (k>>2))*256 + col] * rp[rsel*256 + col];
}

__global__ void k_gatherV(const float* __restrict__ V, float* __restrict__ Vg)
{
    long idx = (long)blockIdx.x*256 + threadIdx.x;
    if (idx >= 4L*NN_*64) return;
    int d = idx & 63;
    int k = (int)((idx >> 6) % NN_);
    int h = (int)((idx >> 6) / NN_);
    Vg[idx] = V[(h*1225 + (k>>2))*256 + ((k&3)<<6) + d];
}

// BC[s][h][j][n]: j<64 from Bt row s*256+h*64+j, j>=64 from Bb row s*256+h*64+(j-64)
__global__ void k_scatterB(const float* __restrict__ Bt, const float* __restrict__ Bb,
                           float* __restrict__ BC)
{
    long idx = (long)blockIdx.x*256 + threadIdx.x;
    if (idx >= 2L*512*NN_) return;
    int n = (int)(idx % NN_);
    int rowo = (int)(idx / NN_);
    int j = rowo & 127;
    int h = (rowo >> 7) & 3;
    int s = rowo >> 9;
    const float* src = (j < 64) ? Bt : Bb;
    BC[idx] = src[(long)(s*256 + h*64 + (j & 63)) * NN_ + n];
}

__global__ void k_softmax(float* __restrict__ al)
{
    long i = (long)blockIdx.x*256 + threadIdx.x;
    if (i >= QK) return;
    float a0 = al[i], a1 = al[i+QK], a2 = al[i+2*QK], a3 = al[i+3*QK];
    float mx = fmaxf(fmaxf(a0,a1), fmaxf(a2,a3));
    float e0 = __expf(a0-mx), e1 = __expf(a1-mx), e2 = __expf(a2-mx), e3 = __expf(a3-mx);
    float inv = 1.f / (e0+e1+e2+e3);
    al[i] = e0*inv; al[i+QK] = e1*inv; al[i+2*QK] = e2*inv; al[i+3*QK] = e3*inv;
}

__device__ __forceinline__ float blk_sum(float v)
{
    __shared__ float sw[8];
    #pragma unroll
    for (int o=16;o;o>>=1) v += __shfl_xor_sync(0xffffffffu, v, o);
    if ((threadIdx.x & 31) == 0) sw[threadIdx.x >> 5] = v;
    __syncthreads();
    float r = 0.f;
    if (threadIdx.x < 32) {
        r = (threadIdx.x < 8) ? sw[threadIdx.x] : 0.f;
        #pragma unroll
        for (int o=4;o;o>>=1) r += __shfl_xor_sync(0xffffffffu, r, o);
        if (threadIdx.x == 0) sw[0] = r;
    }
    __syncthreads();
    r = sw[0];
    __syncthreads();
    return r;
}

__global__ void k_relu_ln_pack(const float* __restrict__ m, const float* __restrict__ H,
                               const float* __restrict__ gg, const float* __restrict__ bb,
                               float* __restrict__ HM)
{
    int row = blockIdx.x, tid = threadIdx.x;
    float x = fmaxf(m[row*256 + tid], 0.f);
    float s1 = blk_sum(x);
    float s2 = blk_sum(x*x);
    float mean = s1 * (1.f/256.f);
    float var  = s2 * (1.f/256.f) - mean*mean;
    float y = (x - mean) * rsqrtf(var + 1e-5f) * gg[tid] + bb[tid];
    HM[row*512 + 256 + tid] = y;
    HM[row*512 + tid]       = H[row*256 + tid];
}

__global__ void k_gate(const float* __restrict__ beta, const float* __restrict__ HM,
                       const float* __restrict__ H, float* __restrict__ out)
{
    int i = blockIdx.x*256 + threadIdx.x;
    if (i >= NN_*256) return;
    int r = i >> 8, c = i & 255;
    float be = beta[i];
    float mv = HM[r*512 + 256 + c];
    out[i] = be*mv + (1.f - be)*H[i];
}

__global__ void k_ln_tanh(float* __restrict__ t, const float* __restrict__ gg,
                          const float* __restrict__ bb)
{
    int row = blockIdx.x, tid = threadIdx.x;
    float x = t[row*256 + tid];
    float s1 = blk_sum(x);
    float s2 = blk_sum(x*x);
    float mean = s1 * (1.f/256.f);
    float var  = s2 * (1.f/256.f) - mean*mean;
    t[row*256 + tid] = tanhf((x - mean) * rsqrtf(var + 1e-6f) * gg[tid] + bb[tid]);
}

// ---------------- host ----------------
extern "C" void kernel_launch(void* const* d_in, const int* in_sizes, int n_in,
                              void* d_out, int out_size)
{
    const float* feature = (const float*)d_in[0];
    const float* adj     = (const float*)d_in[1];
    const float* r       = (const float*)d_in[2];
    const float* Wq = (const float*)d_in[3];  const float* bq = (const float*)d_in[4];
    const float* Wk = (const float*)d_in[5];  const float* bk = (const float*)d_in[6];
    const float* Wv = (const float*)d_in[7];  const float* bv = (const float*)d_in[8];
    const float* Ww = (const float*)d_in[9];  const float* bw = (const float*)d_in[10];
    const float* Wr = (const float*)d_in[11]; const float* br = (const float*)d_in[12];
    const float* Wbeta = (const float*)d_in[13]; const float* bbeta = (const float*)d_in[14];
    const float* ln1g = (const float*)d_in[15]; const float* ln1b = (const float*)d_in[16];
    const float* w1 = (const float*)d_in[17]; const float* b1 = (const float*)d_in[18];
    const float* ln2g = (const float*)d_in[19]; const float* ln2b = (const float*)d_in[20];
    const float* w2 = (const float*)d_in[21];
    const int*   flag = (const int*)d_in[22];
    float* out = (float*)d_out;

    float* g = nullptr;
    cudaGetSymbolAddress((void**)&g, g_buf);
    float* rp = g + O_RP;
    float* PJ = g + O_PJ;
    float* hQ = PJ;  float* hK = PJ + (long)NN_*256;
    float* V  = PJ + 2L*NN_*256;  float* H = PJ + 3L*NN_*256;
    float* Qc = g + O_QC;
    float* CT = g + O_CT;  float* CB = g + O_CB;
    float* Bt = g + O_BT;  float* Bb = g + O_BB;
    float* BC = g + O_BC;  float* Vg = g + O_VG;
    float* M_ = g + O_M;   float* HM = g + O_HM;
    float* BE = g + O_BE;  float* OU = g + O_OU;
    float* T_ = g + O_T;   float* WC = g + O_WC;
    float* B4 = g + O_B4;  float* AL = g + O_AL;

    // 0) pack weights + rp
    k_packW<<<CDIV(4*512*256,256),256>>>(Wq,Wk,Wv,Ww, bq,bk,bv,bw, WC,B4);
    k_rp<<<4,256>>>(r, Wr, br, rp);

    // 1) projections (batched z=4): PJ[z] = feature @ WC[z] + B4[z]
    bfgemm<64><<<dim3(4,39,4),512>>>(feature,512,0, WC,256,512L*256, B4,256,
        PJ,256,(long)NN_*256, NN_,256,512, 0);

    // 2) gathers
    k_gatherQ  <<<(int)CDIV(4L*NN_*128,256),256>>>(hQ, rp, flag, Qc);
    k_gatherCtop<<<CDIV(512*NB1,256),256>>>(hK, rp, flag, CT);
    k_gatherCbot<<<(int)CDIV(512L*NB2,256),256>>>(hK, rp, CB);
    k_gatherV  <<<(int)CDIV(4L*NN_*64,256),256>>>(V, Vg);

    // 3) B-build: Bt = CT @ adj[:708], Bb = CB @ adj[708:]
    bfgemm<128><<<dim3(39,4,1),512>>>(CT,NB1,0, adj,NN_,0, nullptr,0,
        Bt,NN_,0, 512,NN_,NB1, 0);
    bfgemm<128><<<dim3(39,4,1),512>>>(CB,NB2,0, adj + (long)NB1*NN_,NN_,0, nullptr,0,
        Bb,NN_,0, 512,NN_,NB2, 0);

    // 4) BC concat
    k_scatterB<<<(int)CDIV(2L*512*NN_,256),256>>>(Bt, Bb, BC);

    // 5) alpha[h] = Qc[h] @ BC[s][h]   (s=0 for q<708, s=1 for q>=708)
    bfgemm<128><<<dim3(39,6,4),512>>>(Qc,128,(long)NN_*128, BC,NN_,128L*NN_, nullptr,0,
        AL,NN_,QK, NB1,NN_,128, 0);
    bfgemm<128><<<dim3(39,33,4),512>>>(Qc + (long)NB1*128,128,(long)NN_*128,
        BC + 4L*128*NN_,NN_,128L*NN_, nullptr,0,
        AL + (long)NB1*NN_,NN_,QK, NB2,NN_,128, 0);

    // 6) softmax over heads
    k_softmax<<<(int)CDIV(QK,256),256>>>(AL);

    // 7) m[h] = alpha[h] @ Vg[h] -> M_ cols h*64..h*64+63
    bfgemm<64><<<dim3(1,39,4),512>>>(AL,NN_,QK, Vg,64,(long)NN_*64, nullptr,0,
        M_,256,64, NN_,64,NN_, 0);

    // 8) m_ln = LN(relu(m)); HM = [H | m_ln]
    k_relu_ln_pack<<<NN_,256>>>(M_, H, ln1g, ln1b, HM);

    // 9) beta = sigmoid(HM @ Wbeta + bbeta)
    bfgemm<64><<<dim3(4,39,1),512>>>(HM,512,0, Wbeta,256,0, bbeta,0,
        BE,256,0, NN_,256,512, 1);

    // 10) gate
    k_gate<<<CDIV(NN_*256,256),256>>>(BE, HM, H, OU);

    // 11) t = OU @ w1 + b1
    bfgemm<64><<<dim3(4,39,1),512>>>(OU,256,0, w1,256,0, b1,0,
        T_,256,0, NN_,256,256, 0);

    // 12) t = tanh(LN(t))
    k_ln_tanh<<<NN_,256>>>(T_, ln2g, ln2b);

    // 13) out = t @ w2
    bfgemm<64><<<dim3(4,39,1),512>>>(T_,256,0, w2,256,0, nullptr,0,
        out,256,0, NN_,256,256, 0);
}